// round 3
// baseline (speedup 1.0000x reference)
#include <cuda_runtime.h>
#include <cuda_bf16.h>
#include <math.h>

// Problem constants (fixed shapes from reference)
#define BATCH   4
#define NS      2048
#define NTOT    4096
#define KDIM    32
#define TILE    128
#define NTHREADS 256
#define SM_STRIDE 132   // 128 + 4 pad: keeps float4 alignment, reduces STS conflicts

// Device-global scratch (allocation-free per harness rules)
__device__ double g_acc[BATCH];
__device__ float  g_sq[BATCH * NTOT];    // raw squared norms per point
__device__ float  g_qlog[BATCH];         // q * log2(e), q = 1/(16*bw)

// ---------------------------------------------------------------------------
// K1: per-batch prep. One block per batch, 1024 threads (32 warps).
// Warp w handles points i = w, w+32, ... ; lane l handles feature k=l.
// Produces: g_sq[b][i], and from colsum/sumsq the bandwidth -> g_qlog[b].
// Also zeroes g_acc[b].
// ---------------------------------------------------------------------------
__global__ void mmd_prep(const float* __restrict__ src,
                         const float* __restrict__ tgt) {
    const int b = blockIdx.x;
    const int tid = threadIdx.x;
    const int w = tid >> 5;   // warp 0..31
    const int l = tid & 31;   // lane = feature index

    __shared__ float colsh[32 * 33];
    __shared__ float sqsh[32];

    float colp = 0.0f;     // partial column sum for feature l over this warp's points
    float sq_acc = 0.0f;   // lane-0-only accumulator of squared norms

    for (int i = w; i < NTOT; i += 32) {
        const float* row = (i < NS)
            ? src + ((size_t)b * NS + i) * KDIM
            : tgt + ((size_t)b * NS + (i - NS)) * KDIM;
        float v = row[l];
        colp += v;
        float s = v * v;
        #pragma unroll
        for (int off = 16; off > 0; off >>= 1)
            s += __shfl_xor_sync(0xffffffffu, s, off);
        if (l == 0) {
            g_sq[b * NTOT + i] = s;
            sq_acc += s;
        }
    }
    colsh[w * 33 + l] = colp;
    if (l == 0) sqsh[w] = sq_acc;
    __syncthreads();

    if (tid < 32) {
        float cs = 0.0f;
        #pragma unroll
        for (int ww = 0; ww < 32; ww++) cs += colsh[ww * 33 + tid];
        float m2 = cs * cs;          // contributes to |sum_i x_i|^2
        float ss = sqsh[tid];        // contributes to sum_i |x_i|^2
        #pragma unroll
        for (int off = 16; off > 0; off >>= 1) {
            m2 += __shfl_xor_sync(0xffffffffu, m2, off);
            ss += __shfl_xor_sync(0xffffffffu, ss, off);
        }
        if (tid == 0) {
            const float n = (float)NTOT;
            float sumL2 = 2.0f * n * ss - 2.0f * m2;
            float bw = sumL2 / (n * n - n + 1e-8f);
            bw *= 0.25f;  // / KERNEL_MUL ** (KERNEL_NUM // 2) = / 4
            float q = 1.0f / (16.0f * bw);   // smallest-magnitude exponent scale
            g_qlog[b] = q * 1.4426950408889634f;  // fold log2(e) for ex2
            g_acc[b] = 0.0;
        }
    }
}

// ---------------------------------------------------------------------------
// K2: pairwise kernel. grid = (32, 32, 4); 256 threads; 128x128 tile;
// 8x8 register tile per thread. Sign is uniform per tile.
// ---------------------------------------------------------------------------
__device__ __forceinline__ float ex2f(float x) {
    float r;
    asm("ex2.approx.ftz.f32 %0, %1;" : "=f"(r) : "f"(x));
    return r;
}

__global__ __launch_bounds__(NTHREADS, 2)
void mmd_pairs(const float* __restrict__ src,
               const float* __restrict__ tgt) {
    const int b  = blockIdx.z;
    const int bx = blockIdx.x;     // i-tile
    const int by = blockIdx.y;     // j-tile
    const int tid = threadIdx.x;
    const int tx = tid & 15;
    const int ty = tid >> 4;

    const int i0 = bx * TILE;
    const int j0 = by * TILE;

    __shared__ float As[KDIM * SM_STRIDE];
    __shared__ float Bs[KDIM * SM_STRIDE];
    __shared__ float Ra[TILE];
    __shared__ float Rb[TILE];
    __shared__ float red[NTHREADS];

    const float qlog = g_qlog[b];
    const float c2 = 2.0f * qlog;

    const float* bi = (i0 < NS)
        ? src + ((size_t)b * NS + i0) * KDIM
        : tgt + ((size_t)b * NS + (i0 - NS)) * KDIM;
    const float* bj = (j0 < NS)
        ? src + ((size_t)b * NS + j0) * KDIM
        : tgt + ((size_t)b * NS + (j0 - NS)) * KDIM;

    // Load 128 points x 32 floats each, transposed into [k][i] layout.
    #pragma unroll
    for (int f = tid; f < TILE * (KDIM / 4); f += NTHREADS) {
        int p = f >> 3;          // point 0..127
        int c = f & 7;           // float4 chunk 0..7
        float4 v = reinterpret_cast<const float4*>(bi + (size_t)p * KDIM)[c];
        int base = (c * 4) * SM_STRIDE + p;
        As[base] = v.x; As[base + SM_STRIDE] = v.y;
        As[base + 2 * SM_STRIDE] = v.z; As[base + 3 * SM_STRIDE] = v.w;
    }
    #pragma unroll
    for (int f = tid; f < TILE * (KDIM / 4); f += NTHREADS) {
        int p = f >> 3;
        int c = f & 7;
        float4 v = reinterpret_cast<const float4*>(bj + (size_t)p * KDIM)[c];
        int base = (c * 4) * SM_STRIDE + p;
        Bs[base] = v.x; Bs[base + SM_STRIDE] = v.y;
        Bs[base + 2 * SM_STRIDE] = v.z; Bs[base + 3 * SM_STRIDE] = v.w;
    }
    if (tid < TILE) {
        Ra[tid] = g_sq[b * NTOT + i0 + tid] * qlog;
    } else {
        Rb[tid - TILE] = g_sq[b * NTOT + j0 + (tid - TILE)] * qlog;
    }
    __syncthreads();

    float acc[8][8];
    #pragma unroll
    for (int ii = 0; ii < 8; ii++)
        #pragma unroll
        for (int jj = 0; jj < 8; jj++) acc[ii][jj] = 0.0f;

    #pragma unroll 8
    for (int k = 0; k < KDIM; k++) {
        float4 a0 = *reinterpret_cast<const float4*>(&As[k * SM_STRIDE + tx * 8]);
        float4 a1 = *reinterpret_cast<const float4*>(&As[k * SM_STRIDE + tx * 8 + 4]);
        float4 b0 = *reinterpret_cast<const float4*>(&Bs[k * SM_STRIDE + ty * 8]);
        float4 b1 = *reinterpret_cast<const float4*>(&Bs[k * SM_STRIDE + ty * 8 + 4]);
        float av[8] = {a0.x, a0.y, a0.z, a0.w, a1.x, a1.y, a1.z, a1.w};
        float bv[8] = {b0.x, b0.y, b0.z, b0.w, b1.x, b1.y, b1.z, b1.w};
        #pragma unroll
        for (int ii = 0; ii < 8; ii++)
            #pragma unroll
            for (int jj = 0; jj < 8; jj++)
                acc[ii][jj] = fmaf(av[ii], bv[jj], acc[ii][jj]);
    }

    // Epilogue: arg = (2*dot - sq_i - sq_j) * q * log2e; e = 2^arg;
    // 5-bandwidth kernel sum = e + e^2 + e^4 + e^8 + e^16.
    float ra[8], rb[8];
    #pragma unroll
    for (int u = 0; u < 8; u++) {
        ra[u] = Ra[tx * 8 + u];
        rb[u] = Rb[ty * 8 + u];
    }
    float tsum = 0.0f;
    #pragma unroll
    for (int ii = 0; ii < 8; ii++) {
        #pragma unroll
        for (int jj = 0; jj < 8; jj++) {
            float arg = fmaf(acc[ii][jj], c2, -(ra[ii] + rb[jj]));
            float e  = ex2f(arg);
            float e2 = e * e;
            float e4 = e2 * e2;
            float e8 = e4 * e4;
            float e16 = e8 * e8;
            tsum += ((e + e2) + (e4 + e8)) + e16;
        }
    }

    // Block reduction
    red[tid] = tsum;
    __syncthreads();
    #pragma unroll
    for (int s = NTHREADS / 2; s > 0; s >>= 1) {
        if (tid < s) red[tid] += red[tid + s];
        __syncthreads();
    }
    if (tid == 0) {
        // Quadrant sign: + if both tiles in same half (XX, YY), - if cross (XY, YX)
        double sgn = ((bx < 16) == (by < 16)) ? 1.0 : -1.0;
        atomicAdd(&g_acc[b], sgn * (double)red[0]);
    }
}

// ---------------------------------------------------------------------------
// K3: finalize. out[b] = acc[b] * exp(1e-8) / Ns^2
// ---------------------------------------------------------------------------
__global__ void mmd_final(float* __restrict__ out) {
    int t = threadIdx.x;
    if (t < BATCH) {
        double scale = exp(1e-8) / ((double)NS * (double)NS);
        out[t] = (float)(g_acc[t] * scale);
    }
}

extern "C" void kernel_launch(void* const* d_in, const int* in_sizes, int n_in,
                              void* d_out, int out_size) {
    const float* src = (const float*)d_in[0];
    const float* tgt = (const float*)d_in[1];
    float* out = (float*)d_out;

    mmd_prep<<<BATCH, 1024>>>(src, tgt);
    mmd_pairs<<<dim3(NTOT / TILE, NTOT / TILE, BATCH), NTHREADS>>>(src, tgt);
    mmd_final<<<1, 32>>>(out);
}

// round 4
// speedup vs baseline: 2.0437x; 2.0437x over previous
#include <cuda_runtime.h>
#include <cuda_bf16.h>
#include <math.h>

// Problem constants (fixed shapes from reference)
#define BATCH   4
#define NS      2048
#define NTOT    4096
#define KDIM    32
#define TILE    128
#define NTILES  (NTOT / TILE)            // 32
#define NTRI    (NTILES * (NTILES + 1) / 2)  // 528 upper-triangular tiles
#define NTHREADS 256
#define SM_STRIDE 132   // 128 + 4 pad: keeps float4 alignment, reduces STS conflicts
#define PREP_BLOCKS 32  // blocks per batch in prep (128 points each)

// Device-global scratch (allocation-free per harness rules)
__device__ double g_acc[BATCH];
__device__ float  g_sq[BATCH * NTOT];                  // raw squared norms per point
__device__ float  g_qlog[BATCH];                       // q * log2(e), q = 1/(16*bw)
__device__ float  g_pcol[BATCH][PREP_BLOCKS][KDIM];    // partial column sums
__device__ float  g_psq[BATCH][PREP_BLOCKS];           // partial sum of squared norms

// ---------------------------------------------------------------------------
// K_A: squared norms + partial sums. grid = (PREP_BLOCKS, BATCH), 256 threads
// (8 warps). Each block handles 128 points; warp w covers points base+w+8t,
// lane = feature index. No atomics: partials overwritten every call.
// ---------------------------------------------------------------------------
__global__ void mmd_prep_a(const float* __restrict__ src,
                           const float* __restrict__ tgt) {
    const int b   = blockIdx.y;
    const int blk = blockIdx.x;
    const int tid = threadIdx.x;
    const int w = tid >> 5;   // warp 0..7
    const int l = tid & 31;   // lane = feature

    __shared__ float colsh[8 * 33];
    __shared__ float sqsh[8];

    const int base = blk * 128;
    float colp = 0.0f;
    float sq_acc = 0.0f;   // lane-0 accumulator

    #pragma unroll 4
    for (int t = 0; t < 16; t++) {
        int i = base + w + 8 * t;
        const float* row = (i < NS)
            ? src + ((size_t)b * NS + i) * KDIM
            : tgt + ((size_t)b * NS + (i - NS)) * KDIM;
        float v = row[l];
        colp += v;
        float s = v * v;
        #pragma unroll
        for (int off = 16; off > 0; off >>= 1)
            s += __shfl_xor_sync(0xffffffffu, s, off);
        if (l == 0) {
            g_sq[b * NTOT + i] = s;
            sq_acc += s;
        }
    }
    colsh[w * 33 + l] = colp;
    if (l == 0) sqsh[w] = sq_acc;
    __syncthreads();

    if (tid < 32) {
        float cs = 0.0f;
        #pragma unroll
        for (int ww = 0; ww < 8; ww++) cs += colsh[ww * 33 + tid];
        g_pcol[b][blk][tid] = cs;
        if (tid == 0) {
            float ss = 0.0f;
            #pragma unroll
            for (int ww = 0; ww < 8; ww++) ss += sqsh[ww];
            g_psq[b][blk] = ss;
        }
    }
}

// ---------------------------------------------------------------------------
// K_B: bandwidth finalize. 1 block, 128 threads; warp b handles batch b.
// ---------------------------------------------------------------------------
__global__ void mmd_prep_b() {
    const int tid = threadIdx.x;
    const int b = tid >> 5;
    const int l = tid & 31;
    if (b >= BATCH) return;

    float cs = 0.0f;
    #pragma unroll
    for (int blk = 0; blk < PREP_BLOCKS; blk++) cs += g_pcol[b][blk][l];
    float m2 = cs * cs;
    float ss = g_psq[b][l];  // lane l reads partial blk=l (PREP_BLOCKS==32)
    #pragma unroll
    for (int off = 16; off > 0; off >>= 1) {
        m2 += __shfl_xor_sync(0xffffffffu, m2, off);
        ss += __shfl_xor_sync(0xffffffffu, ss, off);
    }
    if (l == 0) {
        const float n = (float)NTOT;
        float sumL2 = 2.0f * n * ss - 2.0f * m2;
        float bw = sumL2 / (n * n - n + 1e-8f);
        bw *= 0.25f;  // / KERNEL_MUL ** (KERNEL_NUM // 2) = / 4
        float q = 1.0f / (16.0f * bw);
        g_qlog[b] = q * 1.4426950408889634f;  // fold log2(e) for ex2
        g_acc[b] = 0.0;
    }
}

// ---------------------------------------------------------------------------
// K2: pairwise kernel, triangular tiling. grid = (NTRI, 1, BATCH).
// Tile (bx, by) with bx <= by; off-diagonal tiles weighted x2 (symmetry of
// both the kernel matrix and the quadrant-sign matrix).
// ---------------------------------------------------------------------------
__device__ __forceinline__ float ex2f(float x) {
    float r;
    asm("ex2.approx.ftz.f32 %0, %1;" : "=f"(r) : "f"(x));
    return r;
}

__global__ __launch_bounds__(NTHREADS, 2)
void mmd_pairs(const float* __restrict__ src,
               const float* __restrict__ tgt) {
    const int b  = blockIdx.z;
    // Decode linear triangular index -> (bx, by), bx <= by
    const int t = blockIdx.x;
    int by = (int)((sqrtf(8.0f * (float)t + 1.0f) - 1.0f) * 0.5f);
    while ((by + 1) * (by + 2) / 2 <= t) by++;
    while (by * (by + 1) / 2 > t) by--;
    const int bx = t - by * (by + 1) / 2;

    const int tid = threadIdx.x;
    const int tx = tid & 15;
    const int ty = tid >> 4;

    const int i0 = bx * TILE;
    const int j0 = by * TILE;

    __shared__ float As[KDIM * SM_STRIDE];
    __shared__ float Bs[KDIM * SM_STRIDE];
    __shared__ float Ra[TILE];
    __shared__ float Rb[TILE];
    __shared__ float red[NTHREADS];

    const float qlog = g_qlog[b];
    const float c2 = 2.0f * qlog;

    const float* bi = (i0 < NS)
        ? src + ((size_t)b * NS + i0) * KDIM
        : tgt + ((size_t)b * NS + (i0 - NS)) * KDIM;
    const float* bj = (j0 < NS)
        ? src + ((size_t)b * NS + j0) * KDIM
        : tgt + ((size_t)b * NS + (j0 - NS)) * KDIM;

    // Load 128 points x 32 floats each, transposed into [k][i] layout.
    #pragma unroll
    for (int f = tid; f < TILE * (KDIM / 4); f += NTHREADS) {
        int p = f >> 3;          // point 0..127
        int c = f & 7;           // float4 chunk 0..7
        float4 v = reinterpret_cast<const float4*>(bi + (size_t)p * KDIM)[c];
        int base = (c * 4) * SM_STRIDE + p;
        As[base] = v.x; As[base + SM_STRIDE] = v.y;
        As[base + 2 * SM_STRIDE] = v.z; As[base + 3 * SM_STRIDE] = v.w;
    }
    #pragma unroll
    for (int f = tid; f < TILE * (KDIM / 4); f += NTHREADS) {
        int p = f >> 3;
        int c = f & 7;
        float4 v = reinterpret_cast<const float4*>(bj + (size_t)p * KDIM)[c];
        int base = (c * 4) * SM_STRIDE + p;
        Bs[base] = v.x; Bs[base + SM_STRIDE] = v.y;
        Bs[base + 2 * SM_STRIDE] = v.z; Bs[base + 3 * SM_STRIDE] = v.w;
    }
    if (tid < TILE) {
        Ra[tid] = g_sq[b * NTOT + i0 + tid] * qlog;
    } else {
        Rb[tid - TILE] = g_sq[b * NTOT + j0 + (tid - TILE)] * qlog;
    }
    __syncthreads();

    float acc[8][8];
    #pragma unroll
    for (int ii = 0; ii < 8; ii++)
        #pragma unroll
        for (int jj = 0; jj < 8; jj++) acc[ii][jj] = 0.0f;

    #pragma unroll 8
    for (int k = 0; k < KDIM; k++) {
        float4 a0 = *reinterpret_cast<const float4*>(&As[k * SM_STRIDE + tx * 8]);
        float4 a1 = *reinterpret_cast<const float4*>(&As[k * SM_STRIDE + tx * 8 + 4]);
        float4 b0 = *reinterpret_cast<const float4*>(&Bs[k * SM_STRIDE + ty * 8]);
        float4 b1 = *reinterpret_cast<const float4*>(&Bs[k * SM_STRIDE + ty * 8 + 4]);
        float av[8] = {a0.x, a0.y, a0.z, a0.w, a1.x, a1.y, a1.z, a1.w};
        float bv[8] = {b0.x, b0.y, b0.z, b0.w, b1.x, b1.y, b1.z, b1.w};
        #pragma unroll
        for (int ii = 0; ii < 8; ii++)
            #pragma unroll
            for (int jj = 0; jj < 8; jj++)
                acc[ii][jj] = fmaf(av[ii], bv[jj], acc[ii][jj]);
    }

    // Epilogue: arg = (2*dot - sq_i - sq_j) * q * log2e; e = 2^arg;
    // 5-bandwidth kernel sum = e + e^2 + e^4 + e^8 + e^16.
    float ra[8], rb[8];
    #pragma unroll
    for (int u = 0; u < 8; u++) {
        ra[u] = Ra[tx * 8 + u];
        rb[u] = Rb[ty * 8 + u];
    }
    float tsum = 0.0f;
    #pragma unroll
    for (int ii = 0; ii < 8; ii++) {
        #pragma unroll
        for (int jj = 0; jj < 8; jj++) {
            float arg = fmaf(acc[ii][jj], c2, -(ra[ii] + rb[jj]));
            float e  = ex2f(arg);
            float e2 = e * e;
            float e4 = e2 * e2;
            float e8 = e4 * e4;
            float e16 = e8 * e8;
            tsum += ((e + e2) + (e4 + e8)) + e16;
        }
    }

    // Block reduction
    red[tid] = tsum;
    __syncthreads();
    #pragma unroll
    for (int s = NTHREADS / 2; s > 0; s >>= 1) {
        if (tid < s) red[tid] += red[tid + s];
        __syncthreads();
    }
    if (tid == 0) {
        // Quadrant sign: + if both tiles in same half (XX, YY), - if cross.
        // Off-diagonal triangular tiles count twice (K and sign both symmetric).
        double wgt = (bx == by) ? 1.0 : 2.0;
        double sgn = ((bx < NTILES / 2) == (by < NTILES / 2)) ? wgt : -wgt;
        atomicAdd(&g_acc[b], sgn * (double)red[0]);
    }
}

// ---------------------------------------------------------------------------
// K3: finalize. out[b] = acc[b] * exp(1e-8) / Ns^2
// ---------------------------------------------------------------------------
__global__ void mmd_final(float* __restrict__ out) {
    int t = threadIdx.x;
    if (t < BATCH) {
        double scale = exp(1e-8) / ((double)NS * (double)NS);
        out[t] = (float)(g_acc[t] * scale);
    }
}

extern "C" void kernel_launch(void* const* d_in, const int* in_sizes, int n_in,
                              void* d_out, int out_size) {
    const float* src = (const float*)d_in[0];
    const float* tgt = (const float*)d_in[1];
    float* out = (float*)d_out;

    mmd_prep_a<<<dim3(PREP_BLOCKS, BATCH), 256>>>(src, tgt);
    mmd_prep_b<<<1, 128>>>();
    mmd_pairs<<<dim3(NTRI, 1, BATCH), NTHREADS>>>(src, tgt);
    mmd_final<<<1, 32>>>(out);
}

// round 6
// speedup vs baseline: 2.1273x; 1.0409x over previous
#include <cuda_runtime.h>
#include <cuda_bf16.h>
#include <math.h>

// Problem constants (fixed shapes from reference)
#define BATCH   4
#define NS      2048
#define NTOT    4096
#define KDIM    32
#define TILE    128
#define NTILES  (NTOT / TILE)                // 32
#define NTRI    (NTILES * (NTILES + 1) / 2)  // 528 upper-triangular tiles
#define NTHREADS 256
#define SM_STRIDE 132   // 128 + 4 pad: float4-aligned, conflict-reducing
#define PREP_BLOCKS 32

// Device-global scratch (allocation-free per harness rules)
__device__ double g_acc[BATCH];
__device__ float  g_sq[BATCH * NTOT];
__device__ float  g_qlog[BATCH];
__device__ float  g_pcol[BATCH][PREP_BLOCKS][KDIM];
__device__ float  g_psq[BATCH][PREP_BLOCKS];
__device__ int    g_done;

// ---- packed f32x2 helpers (sm_103a; ptxas will not auto-fuse these) -------
typedef unsigned long long ull;

__device__ __forceinline__ ull pack2(float lo, float hi) {
    ull r;
    asm("mov.b64 %0, {%1, %2};" : "=l"(r) : "r"(__float_as_uint(lo)), "r"(__float_as_uint(hi)));
    return r;
}
__device__ __forceinline__ void unpack2(float& lo, float& hi, ull v) {
    unsigned int a, b;
    asm("mov.b64 {%0, %1}, %2;" : "=r"(a), "=r"(b) : "l"(v));
    lo = __uint_as_float(a); hi = __uint_as_float(b);
}
#define FMA2(d, a, b, c) asm("fma.rn.f32x2 %0, %1, %2, %3;" : "=l"(d) : "l"(a), "l"(b), "l"(c))
#define MUL2(d, a, b)    asm("mul.rn.f32x2 %0, %1, %2;"     : "=l"(d) : "l"(a), "l"(b))
#define ADD2(d, a, b)    asm("add.rn.f32x2 %0, %1, %2;"     : "=l"(d) : "l"(a), "l"(b))

__device__ __forceinline__ float ex2f(float x) {
    float r;
    asm("ex2.approx.ftz.f32 %0, %1;" : "=f"(r) : "f"(x));
    return r;
}

// ---------------------------------------------------------------------------
// K_A: squared norms + partial column/sq sums. grid=(PREP_BLOCKS, BATCH).
// ---------------------------------------------------------------------------
__global__ void mmd_prep_a(const float* __restrict__ src,
                           const float* __restrict__ tgt) {
    const int b   = blockIdx.y;
    const int blk = blockIdx.x;
    const int tid = threadIdx.x;
    const int w = tid >> 5;
    const int l = tid & 31;

    __shared__ float colsh[8 * 33];
    __shared__ float sqsh[8];

    const int base = blk * 128;
    float colp = 0.0f;
    float sq_acc = 0.0f;

    #pragma unroll 4
    for (int t = 0; t < 16; t++) {
        int i = base + w + 8 * t;
        const float* row = (i < NS)
            ? src + ((size_t)b * NS + i) * KDIM
            : tgt + ((size_t)b * NS + (i - NS)) * KDIM;
        float v = row[l];
        colp += v;
        float s = v * v;
        #pragma unroll
        for (int off = 16; off > 0; off >>= 1)
            s += __shfl_xor_sync(0xffffffffu, s, off);
        if (l == 0) {
            g_sq[b * NTOT + i] = s;
            sq_acc += s;
        }
    }
    colsh[w * 33 + l] = colp;
    if (l == 0) sqsh[w] = sq_acc;
    __syncthreads();

    if (tid < 32) {
        float cs = 0.0f;
        #pragma unroll
        for (int ww = 0; ww < 8; ww++) cs += colsh[ww * 33 + tid];
        g_pcol[b][blk][tid] = cs;
        if (tid == 0) {
            float ss = 0.0f;
            #pragma unroll
            for (int ww = 0; ww < 8; ww++) ss += sqsh[ww];
            g_psq[b][blk] = ss;
        }
    }
}

// ---------------------------------------------------------------------------
// K_B: bandwidth finalize + counter/accumulator reset. 1 block, 128 threads.
// ---------------------------------------------------------------------------
__global__ void mmd_prep_b() {
    const int tid = threadIdx.x;
    const int b = tid >> 5;
    const int l = tid & 31;
    if (tid == 0) g_done = 0;
    if (b >= BATCH) return;

    float cs = 0.0f;
    #pragma unroll
    for (int blk = 0; blk < PREP_BLOCKS; blk++) cs += g_pcol[b][blk][l];
    float m2 = cs * cs;
    float ss = g_psq[b][l];
    #pragma unroll
    for (int off = 16; off > 0; off >>= 1) {
        m2 += __shfl_xor_sync(0xffffffffu, m2, off);
        ss += __shfl_xor_sync(0xffffffffu, ss, off);
    }
    if (l == 0) {
        const float n = (float)NTOT;
        float sumL2 = 2.0f * n * ss - 2.0f * m2;
        float bw = sumL2 / (n * n - n + 1e-8f);
        bw *= 0.25f;  // / KERNEL_MUL ** (KERNEL_NUM // 2)
        float q = 1.0f / (16.0f * bw);
        g_qlog[b] = q * 1.4426950408889634f;
        g_acc[b] = 0.0;
    }
}

// ---------------------------------------------------------------------------
// K2: pairwise kernel, triangular tiling, packed f32x2 math.
// grid = (NTRI, 1, BATCH). Last block overall finalizes the output.
// ---------------------------------------------------------------------------
__global__ __launch_bounds__(NTHREADS, 2)
void mmd_pairs(const float* __restrict__ src,
               const float* __restrict__ tgt,
               float* __restrict__ out) {
    const int b = blockIdx.z;
    const int t = blockIdx.x;
    int by = (int)((sqrtf(8.0f * (float)t + 1.0f) - 1.0f) * 0.5f);
    while ((by + 1) * (by + 2) / 2 <= t) by++;
    while (by * (by + 1) / 2 > t) by--;
    const int bx = t - by * (by + 1) / 2;

    const int tid = threadIdx.x;
    const int tx = tid & 15;
    const int ty = tid >> 4;

    const int i0 = bx * TILE;
    const int j0 = by * TILE;

    __shared__ float As[KDIM * SM_STRIDE];
    __shared__ float Bs[KDIM * SM_STRIDE];
    __shared__ float Ra[TILE];
    __shared__ float Rb[TILE];
    __shared__ float red[NTHREADS];

    const float qlog = g_qlog[b];

    const float* bi = (i0 < NS)
        ? src + ((size_t)b * NS + i0) * KDIM
        : tgt + ((size_t)b * NS + (i0 - NS)) * KDIM;
    const float* bj = (j0 < NS)
        ? src + ((size_t)b * NS + j0) * KDIM
        : tgt + ((size_t)b * NS + (j0 - NS)) * KDIM;

    // Load 128 points x 32 floats, transposed to [k][point] layout.
    #pragma unroll
    for (int f = tid; f < TILE * (KDIM / 4); f += NTHREADS) {
        int p = f >> 3;
        int c = f & 7;
        float4 v = reinterpret_cast<const float4*>(bi + (size_t)p * KDIM)[c];
        int base = (c * 4) * SM_STRIDE + p;
        As[base] = v.x; As[base + SM_STRIDE] = v.y;
        As[base + 2 * SM_STRIDE] = v.z; As[base + 3 * SM_STRIDE] = v.w;
    }
    #pragma unroll
    for (int f = tid; f < TILE * (KDIM / 4); f += NTHREADS) {
        int p = f >> 3;
        int c = f & 7;
        float4 v = reinterpret_cast<const float4*>(bj + (size_t)p * KDIM)[c];
        int base = (c * 4) * SM_STRIDE + p;
        Bs[base] = v.x; Bs[base + SM_STRIDE] = v.y;
        Bs[base + 2 * SM_STRIDE] = v.z; Bs[base + 3 * SM_STRIDE] = v.w;
    }
    if (tid < TILE) {
        Ra[tid] = g_sq[b * NTOT + i0 + tid] * qlog;
    } else {
        Rb[tid - TILE] = g_sq[b * NTOT + j0 + (tid - TILE)] * qlog;
    }
    __syncthreads();

    // Packed accumulators: acc2[ii][j2] = dots for (i=tx*8+ii, j=ty*8+2*j2(+1))
    ull acc2[8][4];
    #pragma unroll
    for (int ii = 0; ii < 8; ii++)
        #pragma unroll
        for (int j2 = 0; j2 < 4; j2++) acc2[ii][j2] = 0ULL;

    #pragma unroll 4
    for (int k = 0; k < KDIM; k++) {
        // b-values: consecutive j -> natural f32x2 pairs straight from shared
        ulonglong2 bq0 = *reinterpret_cast<const ulonglong2*>(&Bs[k * SM_STRIDE + ty * 8]);
        ulonglong2 bq1 = *reinterpret_cast<const ulonglong2*>(&Bs[k * SM_STRIDE + ty * 8 + 4]);
        ull bv2[4] = {bq0.x, bq0.y, bq1.x, bq1.y};
        float4 a0 = *reinterpret_cast<const float4*>(&As[k * SM_STRIDE + tx * 8]);
        float4 a1 = *reinterpret_cast<const float4*>(&As[k * SM_STRIDE + tx * 8 + 4]);
        float av[8] = {a0.x, a0.y, a0.z, a0.w, a1.x, a1.y, a1.z, a1.w};
        ull ad[8];
        #pragma unroll
        for (int ii = 0; ii < 8; ii++) ad[ii] = pack2(av[ii], av[ii]);
        #pragma unroll
        for (int ii = 0; ii < 8; ii++)
            #pragma unroll
            for (int j2 = 0; j2 < 4; j2++)
                FMA2(acc2[ii][j2], ad[ii], bv2[j2], acc2[ii][j2]);
    }

    // Epilogue (packed): arg = 2*qlog*dot - (ra + rb); ksum = e+e^2+e^4+e^8+e^16
    const ull c2d = pack2(2.0f * qlog, 2.0f * qlog);
    ull nra[8], nrb2[4];
    #pragma unroll
    for (int u = 0; u < 8; u++) {
        float r = Ra[tx * 8 + u];
        nra[u] = pack2(-r, -r);
    }
    #pragma unroll
    for (int j2 = 0; j2 < 4; j2++)
        nrb2[j2] = pack2(-Rb[ty * 8 + 2 * j2], -Rb[ty * 8 + 2 * j2 + 1]);

    ull tsum2 = 0ULL;
    #pragma unroll
    for (int ii = 0; ii < 8; ii++) {
        #pragma unroll
        for (int j2 = 0; j2 < 4; j2++) {
            ull nrab, arg2;
            ADD2(nrab, nra[ii], nrb2[j2]);
            FMA2(arg2, acc2[ii][j2], c2d, nrab);
            float alo, ahi;
            unpack2(alo, ahi, arg2);
            ull e = pack2(ex2f(alo), ex2f(ahi));
            ull m2, m4, m8, m16, s1, s2;
            MUL2(m2, e, e);
            MUL2(m4, m2, m2);
            MUL2(m8, m4, m4);
            MUL2(m16, m8, m8);
            ADD2(s1, e, m2);
            ADD2(s2, m4, m8);
            ADD2(s1, s1, s2);
            ADD2(s1, s1, m16);
            ADD2(tsum2, tsum2, s1);
        }
    }
    float tlo, thi;
    unpack2(tlo, thi, tsum2);
    float tsum = tlo + thi;

    // Block reduction
    red[tid] = tsum;
    __syncthreads();
    #pragma unroll
    for (int s = NTHREADS / 2; s > 0; s >>= 1) {
        if (tid < s) red[tid] += red[tid + s];
        __syncthreads();
    }
    if (tid == 0) {
        double wgt = (bx == by) ? 1.0 : 2.0;
        double sgn = ((bx < NTILES / 2) == (by < NTILES / 2)) ? wgt : -wgt;
        atomicAdd(&g_acc[b], sgn * (double)red[0]);
        __threadfence();
        int v = atomicAdd(&g_done, 1);
        if (v == NTRI * BATCH - 1) {
            // Last block overall: finalize output (replaces mmd_final kernel)
            double scale = exp(1e-8) / ((double)NS * (double)NS);
            #pragma unroll
            for (int q = 0; q < BATCH; q++)
                out[q] = (float)(g_acc[q] * scale);
        }
    }
}

extern "C" void kernel_launch(void* const* d_in, const int* in_sizes, int n_in,
                              void* d_out, int out_size) {
    const float* src = (const float*)d_in[0];
    const float* tgt = (const float*)d_in[1];
    float* out = (float*)d_out;

    mmd_prep_a<<<dim3(PREP_BLOCKS, BATCH), 256>>>(src, tgt);
    mmd_prep_b<<<1, 128>>>();
    mmd_pairs<<<dim3(NTRI, 1, BATCH), NTHREADS>>>(src, tgt, out);
}

// round 7
// speedup vs baseline: 2.8823x; 1.3549x over previous
#include <cuda_runtime.h>
#include <cuda_bf16.h>
#include <math.h>

// Problem constants (fixed shapes from reference)
#define BATCH   4
#define NS      2048
#define NTOT    4096
#define KDIM    32
#define TILE    128
#define NTILES  (NTOT / TILE)                // 32
#define NTRI    (NTILES * (NTILES + 1) / 2)  // 528 upper-triangular tiles
#define NTHREADS 256
#define PREP_BLOCKS 64                        // blocks per batch (64 points each)
#define BF_STRIDE 40                          // bf16 elems per row (32 + 8 pad -> 80B, LDSM conflict-free)

// Device-global scratch (allocation-free per harness rules)
__device__ double g_acc[BATCH];
__device__ float  g_qlog[BATCH];
__device__ float  g_pcol[BATCH][PREP_BLOCKS][KDIM];
__device__ float  g_psq[BATCH][PREP_BLOCKS];
__device__ int    g_done;

__device__ __forceinline__ float ex2f(float x) {
    float r;
    asm("ex2.approx.ftz.f32 %0, %1;" : "=f"(r) : "f"(x));
    return r;
}
__device__ __forceinline__ unsigned int su32(const void* p) {
    return (unsigned int)__cvta_generic_to_shared(p);
}

// ---------------------------------------------------------------------------
// K_A: partial column sums + partial sum of squared norms (for bandwidth).
// grid = (PREP_BLOCKS, BATCH), 256 threads. Thread t: point = base + t/4,
// feature chunk c = t&3 covers k = 8c..8c+7. No per-point output needed.
// ---------------------------------------------------------------------------
__global__ void mmd_prep_a(const float* __restrict__ src,
                           const float* __restrict__ tgt) {
    const int b   = blockIdx.y;
    const int blk = blockIdx.x;
    const int tid = threadIdx.x;
    const int c   = tid & 3;

    __shared__ float colacc[KDIM];
    __shared__ float blocksq;

    if (tid < KDIM) colacc[tid] = 0.0f;
    if (tid == 0) blocksq = 0.0f;
    __syncthreads();

    const int i = blk * 64 + (tid >> 2);
    const float* row = (i < NS)
        ? src + ((size_t)b * NS + i) * KDIM
        : tgt + ((size_t)b * NS + (i - NS)) * KDIM;
    float4 v0 = reinterpret_cast<const float4*>(row)[2 * c];
    float4 v1 = reinterpret_cast<const float4*>(row)[2 * c + 1];

    float col[8] = {v0.x, v0.y, v0.z, v0.w, v1.x, v1.y, v1.z, v1.w};
    float s = 0.0f;
    #pragma unroll
    for (int u = 0; u < 8; u++) s += col[u] * col[u];

    // Column sums: reduce over the 8 points in this warp (same c: lanes stride 4)
    #pragma unroll
    for (int u = 0; u < 8; u++) {
        float x = col[u];
        x += __shfl_down_sync(0xffffffffu, x, 16);
        x += __shfl_down_sync(0xffffffffu, x, 8);
        x += __shfl_down_sync(0xffffffffu, x, 4);
        col[u] = x;
    }
    if ((tid & 31) < 4)
        #pragma unroll
        for (int u = 0; u < 8; u++)
            atomicAdd(&colacc[8 * c + u], col[u]);

    // Squared-norm total: full warp reduce, lane0 adds
    #pragma unroll
    for (int off = 16; off > 0; off >>= 1)
        s += __shfl_down_sync(0xffffffffu, s, off);
    if ((tid & 31) == 0) atomicAdd(&blocksq, s);

    __syncthreads();
    if (tid < KDIM) g_pcol[b][blk][tid] = colacc[tid];
    if (tid == 0)   g_psq[b][blk] = blocksq;
}

// ---------------------------------------------------------------------------
// K_B: bandwidth finalize + accumulator/counter reset. 1 block, 128 threads.
// ---------------------------------------------------------------------------
__global__ void mmd_prep_b() {
    const int tid = threadIdx.x;
    const int b = tid >> 5;
    const int l = tid & 31;
    if (tid == 0) g_done = 0;
    if (b >= BATCH) return;

    float cs = 0.0f;
    #pragma unroll
    for (int blk = 0; blk < PREP_BLOCKS; blk++) cs += g_pcol[b][blk][l];
    float m2 = cs * cs;
    float ss = g_psq[b][l] + g_psq[b][32 + l];
    #pragma unroll
    for (int off = 16; off > 0; off >>= 1) {
        m2 += __shfl_xor_sync(0xffffffffu, m2, off);
        ss += __shfl_xor_sync(0xffffffffu, ss, off);
    }
    if (l == 0) {
        const float n = (float)NTOT;
        float sumL2 = 2.0f * n * ss - 2.0f * m2;
        float bw = sumL2 / (n * n - n + 1e-8f);
        bw *= 0.25f;  // / KERNEL_MUL ** (KERNEL_NUM // 2)
        float q = 1.0f / (16.0f * bw);
        g_qlog[b] = q * 1.4426950408889634f;
        g_acc[b] = 0.0;
    }
}

// ---------------------------------------------------------------------------
// mma.sync helpers (legacy warp MMA, bf16 -> fp32)
// ---------------------------------------------------------------------------
__device__ __forceinline__ void mma_bf16(float* c, const unsigned int* a,
                                         const unsigned int* bb) {
    asm volatile(
        "mma.sync.aligned.m16n8k16.row.col.f32.bf16.bf16.f32 "
        "{%0,%1,%2,%3}, {%4,%5,%6,%7}, {%8,%9}, {%0,%1,%2,%3};"
        : "+f"(c[0]), "+f"(c[1]), "+f"(c[2]), "+f"(c[3])
        : "r"(a[0]), "r"(a[1]), "r"(a[2]), "r"(a[3]), "r"(bb[0]), "r"(bb[1]));
}
__device__ __forceinline__ void ldsm_x4(unsigned int* r, unsigned int addr) {
    asm volatile("ldmatrix.sync.aligned.m8n8.x4.shared.b16 {%0,%1,%2,%3}, [%4];"
                 : "=r"(r[0]), "=r"(r[1]), "=r"(r[2]), "=r"(r[3]) : "r"(addr));
}
__device__ __forceinline__ void ldsm_x2(unsigned int* r, unsigned int addr) {
    asm volatile("ldmatrix.sync.aligned.m8n8.x2.shared.b16 {%0,%1}, [%2];"
                 : "=r"(r[0]), "=r"(r[1]) : "r"(addr));
}

// ---------------------------------------------------------------------------
// K2: pairwise kernel. Triangular tiling; Gram via bf16-split tensor MMA
// (b0*b0 + b0*b1 + b1*b0; b1*b1 ~2^-16 dropped). grid = (NTRI, 1, BATCH).
// ---------------------------------------------------------------------------
__global__ __launch_bounds__(NTHREADS, 2)
void mmd_pairs(const float* __restrict__ src,
               const float* __restrict__ tgt,
               float* __restrict__ out) {
    const int b = blockIdx.z;
    const int t = blockIdx.x;
    int by = (int)((sqrtf(8.0f * (float)t + 1.0f) - 1.0f) * 0.5f);
    while ((by + 1) * (by + 2) / 2 <= t) by++;
    while (by * (by + 1) / 2 > t) by--;
    const int bx = t - by * (by + 1) / 2;

    const int tid  = threadIdx.x;
    const int lane = tid & 31;
    const int w    = tid >> 5;   // warp 0..7 -> rows 16w..16w+15

    const int i0 = bx * TILE;
    const int j0 = by * TILE;

    __shared__ __nv_bfloat16 A0[TILE * BF_STRIDE];
    __shared__ __nv_bfloat16 A1[TILE * BF_STRIDE];
    __shared__ __nv_bfloat16 B0[TILE * BF_STRIDE];
    __shared__ __nv_bfloat16 B1[TILE * BF_STRIDE];
    __shared__ float Ra[TILE];
    __shared__ float Rb[TILE];
    __shared__ float red[NTHREADS];

    const float qlog = g_qlog[b];

    const float* bi = (i0 < NS)
        ? src + ((size_t)b * NS + i0) * KDIM
        : tgt + ((size_t)b * NS + (i0 - NS)) * KDIM;
    const float* bj = (j0 < NS)
        ? src + ((size_t)b * NS + j0) * KDIM
        : tgt + ((size_t)b * NS + (j0 - NS)) * KDIM;

    // Load + split into bf16 hi/lo; also per-point squared norms via
    // 8-lane segmented shuffle (threads f..f+7 share a point).
    #pragma unroll
    for (int it = 0; it < 2; it++) {
        const float* srcp = it ? bj : bi;
        __nv_bfloat16* D0 = it ? B0 : A0;
        __nv_bfloat16* D1 = it ? B1 : A1;
        float* R = it ? Rb : Ra;
        #pragma unroll
        for (int f = tid; f < TILE * (KDIM / 4); f += NTHREADS) {
            int p = f >> 3;          // point 0..127
            int c = f & 7;           // float4 chunk
            float4 v = reinterpret_cast<const float4*>(srcp + (size_t)p * KDIM)[c];
            __nv_bfloat16 h0x = __float2bfloat16_rn(v.x);
            __nv_bfloat16 h0y = __float2bfloat16_rn(v.y);
            __nv_bfloat16 h0z = __float2bfloat16_rn(v.z);
            __nv_bfloat16 h0w = __float2bfloat16_rn(v.w);
            __nv_bfloat16 h1x = __float2bfloat16_rn(v.x - __bfloat162float(h0x));
            __nv_bfloat16 h1y = __float2bfloat16_rn(v.y - __bfloat162float(h0y));
            __nv_bfloat16 h1z = __float2bfloat16_rn(v.z - __bfloat162float(h0z));
            __nv_bfloat16 h1w = __float2bfloat16_rn(v.w - __bfloat162float(h0w));
            int base = p * BF_STRIDE + c * 4;
            *reinterpret_cast<__nv_bfloat162*>(&D0[base])     = __nv_bfloat162(h0x, h0y);
            *reinterpret_cast<__nv_bfloat162*>(&D0[base + 2]) = __nv_bfloat162(h0z, h0w);
            *reinterpret_cast<__nv_bfloat162*>(&D1[base])     = __nv_bfloat162(h1x, h1y);
            *reinterpret_cast<__nv_bfloat162*>(&D1[base + 2]) = __nv_bfloat162(h1z, h1w);
            float s = v.x * v.x + v.y * v.y + v.z * v.z + v.w * v.w;
            s += __shfl_down_sync(0xffffffffu, s, 4, 8);
            s += __shfl_down_sync(0xffffffffu, s, 2, 8);
            s += __shfl_down_sync(0xffffffffu, s, 1, 8);
            if (c == 0) R[p] = s * qlog;
        }
    }
    __syncthreads();

    // Mainloop: each warp computes rows [16w,16w+16) x all 128 j.
    float acc[16][4];
    #pragma unroll
    for (int nt = 0; nt < 16; nt++)
        #pragma unroll
        for (int u = 0; u < 4; u++) acc[nt][u] = 0.0f;

    const int arow = 16 * w + (lane & 15);
    #pragma unroll
    for (int ks = 0; ks < 2; ks++) {
        const int k0 = 16 * ks;
        const int acol = k0 + ((lane >> 4) << 3);
        unsigned int a0[4], a1[4];
        ldsm_x4(a0, su32(&A0[arow * BF_STRIDE + acol]));
        ldsm_x4(a1, su32(&A1[arow * BF_STRIDE + acol]));
        const int brow_off = (lane & 7) * BF_STRIDE + k0 + (lane & 8);
        #pragma unroll
        for (int nt = 0; nt < 16; nt++) {
            unsigned int bb0[2], bb1[2];
            ldsm_x2(bb0, su32(&B0[nt * 8 * BF_STRIDE + brow_off]));
            ldsm_x2(bb1, su32(&B1[nt * 8 * BF_STRIDE + brow_off]));
            mma_bf16(acc[nt], a0, bb0);   // hi*hi
            mma_bf16(acc[nt], a0, bb1);   // hi*lo
            mma_bf16(acc[nt], a1, bb0);   // lo*hi
        }
    }

    // Epilogue. D frag (thread lane): rows r=16w+g, r+8 (g=lane>>2);
    // cols j = 8nt + 2*(lane&3) + {0,1}.
    const float c2 = 2.0f * qlog;
    const int g = lane >> 2;
    const float ra0 = Ra[16 * w + g];
    const float ra1 = Ra[16 * w + g + 8];
    const int jb = 2 * (lane & 3);
    float tsum = 0.0f;
    #pragma unroll
    for (int nt = 0; nt < 16; nt++) {
        float rb0 = Rb[8 * nt + jb];
        float rb1 = Rb[8 * nt + jb + 1];
        float args[4] = {
            fmaf(acc[nt][0], c2, -(ra0 + rb0)),
            fmaf(acc[nt][1], c2, -(ra0 + rb1)),
            fmaf(acc[nt][2], c2, -(ra1 + rb0)),
            fmaf(acc[nt][3], c2, -(ra1 + rb1)),
        };
        #pragma unroll
        for (int u = 0; u < 4; u++) {
            float e  = ex2f(args[u]);
            float e2 = e * e;
            float e4 = e2 * e2;
            float e8 = e4 * e4;
            float e16 = e8 * e8;
            tsum += ((e + e2) + (e4 + e8)) + e16;
        }
    }

    // Block reduction
    red[tid] = tsum;
    __syncthreads();
    #pragma unroll
    for (int s = NTHREADS / 2; s > 0; s >>= 1) {
        if (tid < s) red[tid] += red[tid + s];
        __syncthreads();
    }
    if (tid == 0) {
        double wgt = (bx == by) ? 1.0 : 2.0;
        double sgn = ((bx < NTILES / 2) == (by < NTILES / 2)) ? wgt : -wgt;
        atomicAdd(&g_acc[b], sgn * (double)red[0]);
        __threadfence();
        int v = atomicAdd(&g_done, 1);
        if (v == NTRI * BATCH - 1) {
            double scale = exp(1e-8) / ((double)NS * (double)NS);
            #pragma unroll
            for (int q = 0; q < BATCH; q++)
                out[q] = (float)(g_acc[q] * scale);
        }
    }
}

extern "C" void kernel_launch(void* const* d_in, const int* in_sizes, int n_in,
                              void* d_out, int out_size) {
    const float* src = (const float*)d_in[0];
    const float* tgt = (const float*)d_in[1];
    float* out = (float*)d_out;

    mmd_prep_a<<<dim3(PREP_BLOCKS, BATCH), 256>>>(src, tgt);
    mmd_prep_b<<<1, 128>>>();
    mmd_pairs<<<dim3(NTRI, 1, BATCH), NTHREADS>>>(src, tgt, out);
}

// round 8
// speedup vs baseline: 3.0615x; 1.0622x over previous
#include <cuda_runtime.h>
#include <cuda_bf16.h>
#include <math.h>

// Problem constants (fixed shapes from reference)
#define BATCH   4
#define NS      2048
#define NTOT    4096
#define KDIM    32
#define TILE    128
#define NTILES  (NTOT / TILE)                // 32
#define NTRI    (NTILES * (NTILES + 1) / 2)  // 528 upper-triangular tiles
#define NTHREADS 256
#define PREP_BLOCKS 64                        // blocks per batch (64 points each)
#define BF_STRIDE 40                          // bf16/row: 32 + 8 pad (80B) -> LDSM conflict-free

// Device-global scratch (allocation-free per harness rules)
__device__ double g_acc[BATCH];
__device__ float  g_qlog[BATCH];
__device__ float  g_sq[BATCH * NTOT];
__device__ float  g_pcol[BATCH][PREP_BLOCKS][KDIM];
__device__ float  g_psq[BATCH][PREP_BLOCKS];
__device__ int    g_done;
// Precomputed bf16 two-term split of all points (1 MB each; L2-resident)
__device__ __nv_bfloat16 g_hi[BATCH * NTOT * KDIM];
__device__ __nv_bfloat16 g_lo[BATCH * NTOT * KDIM];

__device__ __forceinline__ float ex2f(float x) {
    float r;
    asm("ex2.approx.ftz.f32 %0, %1;" : "=f"(r) : "f"(x));
    return r;
}
__device__ __forceinline__ unsigned int su32(const void* p) {
    return (unsigned int)__cvta_generic_to_shared(p);
}
__device__ __forceinline__ unsigned int packbf(float a, float b) {
    __nv_bfloat162 h(__float2bfloat16_rn(a), __float2bfloat16_rn(b));
    return *reinterpret_cast<unsigned int*>(&h);
}

// ---------------------------------------------------------------------------
// K_A: bf16 split + per-point sq norms + partial column/sq sums.
// grid = (PREP_BLOCKS, BATCH), 256 threads. Thread t: point = base + t/4,
// feature chunk c = t&3 covers k = 8c..8c+7.
// ---------------------------------------------------------------------------
__global__ void mmd_prep_a(const float* __restrict__ src,
                           const float* __restrict__ tgt) {
    const int b   = blockIdx.y;
    const int blk = blockIdx.x;
    const int tid = threadIdx.x;
    const int c   = tid & 3;

    __shared__ float colacc[KDIM];
    __shared__ float blocksq;

    if (tid < KDIM) colacc[tid] = 0.0f;
    if (tid == 0) blocksq = 0.0f;
    __syncthreads();

    const int i = blk * 64 + (tid >> 2);
    const float* row = (i < NS)
        ? src + ((size_t)b * NS + i) * KDIM
        : tgt + ((size_t)b * NS + (i - NS)) * KDIM;
    float4 v0 = reinterpret_cast<const float4*>(row)[2 * c];
    float4 v1 = reinterpret_cast<const float4*>(row)[2 * c + 1];
    float col[8] = {v0.x, v0.y, v0.z, v0.w, v1.x, v1.y, v1.z, v1.w};

    // bf16 hi/lo split, stored as uint4 (8 bf16) per array
    float hi[8], lo[8];
    #pragma unroll
    for (int u = 0; u < 8; u++) {
        hi[u] = __bfloat162float(__float2bfloat16_rn(col[u]));
        lo[u] = col[u] - hi[u];
    }
    const size_t boff = (((size_t)b * NTOT + i) * KDIM + 8 * c) / 8;  // uint4 index
    reinterpret_cast<uint4*>(g_hi)[boff] =
        make_uint4(packbf(hi[0], hi[1]), packbf(hi[2], hi[3]),
                   packbf(hi[4], hi[5]), packbf(hi[6], hi[7]));
    reinterpret_cast<uint4*>(g_lo)[boff] =
        make_uint4(packbf(lo[0], lo[1]), packbf(lo[2], lo[3]),
                   packbf(lo[4], lo[5]), packbf(lo[6], lo[7]));

    float s = 0.0f;
    #pragma unroll
    for (int u = 0; u < 8; u++) s += col[u] * col[u];

    // Per-point sq norm: reduce over 4-thread group sharing this point
    float spt = s;
    spt += __shfl_xor_sync(0xffffffffu, spt, 1);
    spt += __shfl_xor_sync(0xffffffffu, spt, 2);
    if (c == 0) g_sq[b * NTOT + i] = spt;

    // Column sums: reduce over the 8 points in this warp (same c: stride 4)
    #pragma unroll
    for (int u = 0; u < 8; u++) {
        float x = col[u];
        x += __shfl_down_sync(0xffffffffu, x, 16);
        x += __shfl_down_sync(0xffffffffu, x, 8);
        x += __shfl_down_sync(0xffffffffu, x, 4);
        col[u] = x;
    }
    if ((tid & 31) < 4)
        #pragma unroll
        for (int u = 0; u < 8; u++)
            atomicAdd(&colacc[8 * c + u], col[u]);

    // Block sq total (full warp reduce of raw s)
    #pragma unroll
    for (int off = 16; off > 0; off >>= 1)
        s += __shfl_down_sync(0xffffffffu, s, off);
    if ((tid & 31) == 0) atomicAdd(&blocksq, s);

    __syncthreads();
    if (tid < KDIM) g_pcol[b][blk][tid] = colacc[tid];
    if (tid == 0)   g_psq[b][blk] = blocksq;
}

// ---------------------------------------------------------------------------
// K_B: bandwidth finalize + accumulator/counter reset. 1 block, 128 threads.
// ---------------------------------------------------------------------------
__global__ void mmd_prep_b() {
    const int tid = threadIdx.x;
    const int b = tid >> 5;
    const int l = tid & 31;
    if (tid == 0) g_done = 0;
    if (b >= BATCH) return;

    float cs = 0.0f;
    #pragma unroll
    for (int blk = 0; blk < PREP_BLOCKS; blk++) cs += g_pcol[b][blk][l];
    float m2 = cs * cs;
    float ss = g_psq[b][l] + g_psq[b][32 + l];
    #pragma unroll
    for (int off = 16; off > 0; off >>= 1) {
        m2 += __shfl_xor_sync(0xffffffffu, m2, off);
        ss += __shfl_xor_sync(0xffffffffu, ss, off);
    }
    if (l == 0) {
        const float n = (float)NTOT;
        float sumL2 = 2.0f * n * ss - 2.0f * m2;
        float bw = sumL2 / (n * n - n + 1e-8f);
        bw *= 0.25f;  // / KERNEL_MUL ** (KERNEL_NUM // 2)
        float q = 1.0f / (16.0f * bw);
        g_qlog[b] = q * 1.4426950408889634f;
        g_acc[b] = 0.0;
    }
}

// ---------------------------------------------------------------------------
// mma.sync helpers (legacy warp MMA, bf16 -> fp32)
// ---------------------------------------------------------------------------
__device__ __forceinline__ void mma_bf16(float* c, const unsigned int* a,
                                         const unsigned int* bb) {
    asm volatile(
        "mma.sync.aligned.m16n8k16.row.col.f32.bf16.bf16.f32 "
        "{%0,%1,%2,%3}, {%4,%5,%6,%7}, {%8,%9}, {%0,%1,%2,%3};"
        : "+f"(c[0]), "+f"(c[1]), "+f"(c[2]), "+f"(c[3])
        : "r"(a[0]), "r"(a[1]), "r"(a[2]), "r"(a[3]), "r"(bb[0]), "r"(bb[1]));
}
__device__ __forceinline__ void ldsm_x4(unsigned int* r, unsigned int addr) {
    asm volatile("ldmatrix.sync.aligned.m8n8.x4.shared.b16 {%0,%1,%2,%3}, [%4];"
                 : "=r"(r[0]), "=r"(r[1]), "=r"(r[2]), "=r"(r[3]) : "r"(addr));
}

// ---------------------------------------------------------------------------
// K2: pairwise kernel. Triangular tiling; Gram via bf16-split tensor MMA
// (hi*hi + hi*lo + lo*hi). grid = (NTRI, 1, BATCH).
// ---------------------------------------------------------------------------
__global__ __launch_bounds__(NTHREADS, 2)
void mmd_pairs(float* __restrict__ out) {
    const int b = blockIdx.z;
    const int t = blockIdx.x;
    int by = (int)((sqrtf(8.0f * (float)t + 1.0f) - 1.0f) * 0.5f);
    while ((by + 1) * (by + 2) / 2 <= t) by++;
    while (by * (by + 1) / 2 > t) by--;
    const int bx = t - by * (by + 1) / 2;

    const int tid  = threadIdx.x;
    const int lane = tid & 31;
    const int w    = tid >> 5;   // warp 0..7 -> rows 16w..16w+15

    const int i0 = bx * TILE;
    const int j0 = by * TILE;

    __shared__ __nv_bfloat16 A0[TILE * BF_STRIDE];
    __shared__ __nv_bfloat16 A1[TILE * BF_STRIDE];
    __shared__ __nv_bfloat16 B0[TILE * BF_STRIDE];
    __shared__ __nv_bfloat16 B1[TILE * BF_STRIDE];
    __shared__ float Ra[TILE];
    __shared__ float Rb[TILE];
    __shared__ float red[8];

    const float qlog = g_qlog[b];

    // Prologue: straight uint4 copies of precomputed bf16 splits (L2-resident)
    const uint4* srcA0 = reinterpret_cast<const uint4*>(g_hi + ((size_t)b * NTOT + i0) * KDIM);
    const uint4* srcA1 = reinterpret_cast<const uint4*>(g_lo + ((size_t)b * NTOT + i0) * KDIM);
    const uint4* srcB0 = reinterpret_cast<const uint4*>(g_hi + ((size_t)b * NTOT + j0) * KDIM);
    const uint4* srcB1 = reinterpret_cast<const uint4*>(g_lo + ((size_t)b * NTOT + j0) * KDIM);
    #pragma unroll
    for (int f = tid; f < TILE * 4; f += NTHREADS) {
        int p = f >> 2, q = f & 3;   // point, 8-elem chunk
        *reinterpret_cast<uint4*>(&A0[p * BF_STRIDE + q * 8]) = srcA0[f];
        *reinterpret_cast<uint4*>(&A1[p * BF_STRIDE + q * 8]) = srcA1[f];
        *reinterpret_cast<uint4*>(&B0[p * BF_STRIDE + q * 8]) = srcB0[f];
        *reinterpret_cast<uint4*>(&B1[p * BF_STRIDE + q * 8]) = srcB1[f];
    }
    if (tid < TILE) {
        Ra[tid] = g_sq[b * NTOT + i0 + tid] * qlog;
    } else {
        Rb[tid - TILE] = g_sq[b * NTOT + j0 + (tid - TILE)] * qlog;
    }
    __syncthreads();

    // Mainloop: each warp computes rows [16w,16w+16) x all 128 j.
    float acc[16][4];
    #pragma unroll
    for (int nt = 0; nt < 16; nt++)
        #pragma unroll
        for (int u = 0; u < 4; u++) acc[nt][u] = 0.0f;

    const int arow = 16 * w + (lane & 15);
    #pragma unroll
    for (int ks = 0; ks < 2; ks++) {
        const int k0 = 16 * ks;
        const int acol = k0 + ((lane >> 4) << 3);
        unsigned int a0[4], a1[4];
        ldsm_x4(a0, su32(&A0[arow * BF_STRIDE + acol]));
        ldsm_x4(a1, su32(&A1[arow * BF_STRIDE + acol]));
        // B x4: matrices {nt=2*nt2: k0..k0+15} and {nt=2*nt2+1: k0..k0+15}
        const int brow = ((lane >> 4) << 3) + (lane & 7);
        const int bcol = k0 + (lane & 8);
        #pragma unroll
        for (int nt2 = 0; nt2 < 8; nt2++) {
            unsigned int bb0[4], bb1[4];
            ldsm_x4(bb0, su32(&B0[(16 * nt2 + brow) * BF_STRIDE + bcol]));
            ldsm_x4(bb1, su32(&B1[(16 * nt2 + brow) * BF_STRIDE + bcol]));
            mma_bf16(acc[2 * nt2],     a0, bb0);      // hi*hi
            mma_bf16(acc[2 * nt2],     a0, bb1);      // hi*lo
            mma_bf16(acc[2 * nt2],     a1, bb0);      // lo*hi
            mma_bf16(acc[2 * nt2 + 1], a0, bb0 + 2);
            mma_bf16(acc[2 * nt2 + 1], a0, bb1 + 2);
            mma_bf16(acc[2 * nt2 + 1], a1, bb0 + 2);
        }
    }

    // Epilogue. D frag: rows r=16w+g, r+8 (g=lane>>2); cols j=8nt+2*(lane&3)+{0,1}
    const float c2 = 2.0f * qlog;
    const int g = lane >> 2;
    const float ra0 = Ra[16 * w + g];
    const float ra1 = Ra[16 * w + g + 8];
    const int jb = 2 * (lane & 3);
    float tsA = 0.0f, tsB = 0.0f, tsC = 0.0f;
    #pragma unroll
    for (int nt = 0; nt < 16; nt++) {
        float rb0 = Rb[8 * nt + jb];
        float rb1 = Rb[8 * nt + jb + 1];
        float args[4] = {
            fmaf(acc[nt][0], c2, -(ra0 + rb0)),
            fmaf(acc[nt][1], c2, -(ra0 + rb1)),
            fmaf(acc[nt][2], c2, -(ra1 + rb0)),
            fmaf(acc[nt][3], c2, -(ra1 + rb1)),
        };
        #pragma unroll
        for (int u = 0; u < 4; u++) {
            float e  = ex2f(args[u]);
            float e2 = e * e;
            float e4 = e2 * e2;
            float e8 = e4 * e4;
            tsA += e + e2;
            tsB += e4 + e8;
            tsC = fmaf(e8, e8, tsC);   // e^16
        }
    }
    float tsum = (tsA + tsB) + tsC;

    // Warp-shuffle reduction, then tiny cross-warp pass
    #pragma unroll
    for (int off = 16; off > 0; off >>= 1)
        tsum += __shfl_xor_sync(0xffffffffu, tsum, off);
    if (lane == 0) red[w] = tsum;
    __syncthreads();
    if (tid == 0) {
        float blocksum = 0.0f;
        #pragma unroll
        for (int u = 0; u < 8; u++) blocksum += red[u];
        double wgt = (bx == by) ? 1.0 : 2.0;
        double sgn = ((bx < NTILES / 2) == (by < NTILES / 2)) ? wgt : -wgt;
        atomicAdd(&g_acc[b], sgn * (double)blocksum);
        __threadfence();
        int v = atomicAdd(&g_done, 1);
        if (v == NTRI * BATCH - 1) {
            double scale = exp(1e-8) / ((double)NS * (double)NS);
            #pragma unroll
            for (int q = 0; q < BATCH; q++)
                out[q] = (float)(g_acc[q] * scale);
        }
    }
}

extern "C" void kernel_launch(void* const* d_in, const int* in_sizes, int n_in,
                              void* d_out, int out_size) {
    const float* src = (const float*)d_in[0];
    const float* tgt = (const float*)d_in[1];
    float* out = (float*)d_out;

    mmd_prep_a<<<dim3(PREP_BLOCKS, BATCH), 256>>>(src, tgt);
    mmd_prep_b<<<1, 128>>>();
    mmd_pairs<<<dim3(NTRI, 1, BATCH), NTHREADS>>>(out);
}

// round 9
// speedup vs baseline: 3.2874x; 1.0738x over previous
#include <cuda_runtime.h>
#include <cuda_bf16.h>
#include <math.h>

// Problem constants (fixed shapes from reference)
#define BATCH   4
#define NS      2048
#define NTOT    4096
#define KDIM    32
#define TILE    128
#define NTILES  (NTOT / TILE)                // 32
#define NTRI    (NTILES * (NTILES + 1) / 2)  // 528 upper-triangular tiles
#define NTHREADS 256
#define PREP_BLOCKS 64                        // blocks per batch (64 points each)
#define BF_STRIDE 40                          // bf16/row: 32 + 8 pad (80B) -> LDSM conflict-free

// Device-global scratch (allocation-free per harness rules)
__device__ double g_acc[BATCH];
__device__ float  g_sq[BATCH * NTOT];
__device__ float  g_pcol[BATCH][PREP_BLOCKS][KDIM];
__device__ float  g_psq[BATCH][PREP_BLOCKS];
__device__ int    g_done;
// Precomputed bf16 two-term split of all points (1 MB each; L2-resident)
__device__ __nv_bfloat16 g_hi[BATCH * NTOT * KDIM];
__device__ __nv_bfloat16 g_lo[BATCH * NTOT * KDIM];

__device__ __forceinline__ float ex2f(float x) {
    float r;
    asm("ex2.approx.ftz.f32 %0, %1;" : "=f"(r) : "f"(x));
    return r;
}
__device__ __forceinline__ unsigned int su32(const void* p) {
    return (unsigned int)__cvta_generic_to_shared(p);
}
__device__ __forceinline__ unsigned int packbf(float a, float b) {
    __nv_bfloat162 h(__float2bfloat16_rn(a), __float2bfloat16_rn(b));
    return *reinterpret_cast<unsigned int*>(&h);
}

// ---------------------------------------------------------------------------
// K_A: bf16 split + per-point sq norms + partial column/sq sums.
// grid = (PREP_BLOCKS, BATCH), 256 threads. Thread t: point = base + t/4,
// feature chunk c = t&3 covers k = 8c..8c+7. Block (0,0) also resets
// the accumulators (safe: no other prep block touches them).
// ---------------------------------------------------------------------------
__global__ void mmd_prep_a(const float* __restrict__ src,
                           const float* __restrict__ tgt) {
    const int b   = blockIdx.y;
    const int blk = blockIdx.x;
    const int tid = threadIdx.x;
    const int c   = tid & 3;

    if (b == 0 && blk == 0) {
        if (tid < BATCH) g_acc[tid] = 0.0;
        if (tid == BATCH) g_done = 0;
    }

    __shared__ float colacc[KDIM];
    __shared__ float blocksq;

    if (tid < KDIM) colacc[tid] = 0.0f;
    if (tid == 0) blocksq = 0.0f;
    __syncthreads();

    const int i = blk * 64 + (tid >> 2);
    const float* row = (i < NS)
        ? src + ((size_t)b * NS + i) * KDIM
        : tgt + ((size_t)b * NS + (i - NS)) * KDIM;
    float4 v0 = reinterpret_cast<const float4*>(row)[2 * c];
    float4 v1 = reinterpret_cast<const float4*>(row)[2 * c + 1];
    float col[8] = {v0.x, v0.y, v0.z, v0.w, v1.x, v1.y, v1.z, v1.w};

    // bf16 hi/lo split, stored as uint4 (8 bf16) per array
    float hi[8], lo[8];
    #pragma unroll
    for (int u = 0; u < 8; u++) {
        hi[u] = __bfloat162float(__float2bfloat16_rn(col[u]));
        lo[u] = col[u] - hi[u];
    }
    const size_t boff = (((size_t)b * NTOT + i) * KDIM + 8 * c) / 8;  // uint4 index
    reinterpret_cast<uint4*>(g_hi)[boff] =
        make_uint4(packbf(hi[0], hi[1]), packbf(hi[2], hi[3]),
                   packbf(hi[4], hi[5]), packbf(hi[6], hi[7]));
    reinterpret_cast<uint4*>(g_lo)[boff] =
        make_uint4(packbf(lo[0], lo[1]), packbf(lo[2], lo[3]),
                   packbf(lo[4], lo[5]), packbf(lo[6], lo[7]));

    float s = 0.0f;
    #pragma unroll
    for (int u = 0; u < 8; u++) s += col[u] * col[u];

    // Per-point sq norm: reduce over 4-thread group sharing this point
    float spt = s;
    spt += __shfl_xor_sync(0xffffffffu, spt, 1);
    spt += __shfl_xor_sync(0xffffffffu, spt, 2);
    if (c == 0) g_sq[b * NTOT + i] = spt;

    // Column sums: reduce over the 8 points in this warp (same c: stride 4)
    #pragma unroll
    for (int u = 0; u < 8; u++) {
        float x = col[u];
        x += __shfl_down_sync(0xffffffffu, x, 16);
        x += __shfl_down_sync(0xffffffffu, x, 8);
        x += __shfl_down_sync(0xffffffffu, x, 4);
        col[u] = x;
    }
    if ((tid & 31) < 4)
        #pragma unroll
        for (int u = 0; u < 8; u++)
            atomicAdd(&colacc[8 * c + u], col[u]);

    // Block sq total (full warp reduce of raw s)
    #pragma unroll
    for (int off = 16; off > 0; off >>= 1)
        s += __shfl_down_sync(0xffffffffu, s, off);
    if ((tid & 31) == 0) atomicAdd(&blocksq, s);

    __syncthreads();
    if (tid < KDIM) g_pcol[b][blk][tid] = colacc[tid];
    if (tid == 0)   g_psq[b][blk] = blocksq;
}

// ---------------------------------------------------------------------------
// mma.sync helpers (legacy warp MMA, bf16 -> fp32)
// ---------------------------------------------------------------------------
__device__ __forceinline__ void mma_bf16(float* c, const unsigned int* a,
                                         const unsigned int* bb) {
    asm volatile(
        "mma.sync.aligned.m16n8k16.row.col.f32.bf16.bf16.f32 "
        "{%0,%1,%2,%3}, {%4,%5,%6,%7}, {%8,%9}, {%0,%1,%2,%3};"
        : "+f"(c[0]), "+f"(c[1]), "+f"(c[2]), "+f"(c[3])
        : "r"(a[0]), "r"(a[1]), "r"(a[2]), "r"(a[3]), "r"(bb[0]), "r"(bb[1]));
}
__device__ __forceinline__ void ldsm_x4(unsigned int* r, unsigned int addr) {
    asm volatile("ldmatrix.sync.aligned.m8n8.x4.shared.b16 {%0,%1,%2,%3}, [%4];"
                 : "=r"(r[0]), "=r"(r[1]), "=r"(r[2]), "=r"(r[3]) : "r"(addr));
}

// ---------------------------------------------------------------------------
// K2: pairwise kernel. Triangular tiling; Gram via bf16-split tensor MMA
// (hi*hi + hi*lo + lo*hi). In-block bandwidth reduction (no prep_b launch).
// grid = (NTRI, 1, BATCH).
// ---------------------------------------------------------------------------
__global__ __launch_bounds__(NTHREADS, 2)
void mmd_pairs(float* __restrict__ out) {
    const int b = blockIdx.z;
    const int t = blockIdx.x;
    int by = (int)((sqrtf(8.0f * (float)t + 1.0f) - 1.0f) * 0.5f);
    while ((by + 1) * (by + 2) / 2 <= t) by++;
    while (by * (by + 1) / 2 > t) by--;
    const int bx = t - by * (by + 1) / 2;

    const int tid  = threadIdx.x;
    const int lane = tid & 31;
    const int w    = tid >> 5;   // warp 0..7 -> rows 16w..16w+15

    const int i0 = bx * TILE;
    const int j0 = by * TILE;

    __shared__ __nv_bfloat16 A0[TILE * BF_STRIDE];
    __shared__ __nv_bfloat16 A1[TILE * BF_STRIDE];
    __shared__ __nv_bfloat16 B0[TILE * BF_STRIDE];
    __shared__ __nv_bfloat16 B1[TILE * BF_STRIDE];
    __shared__ float Ra[TILE];
    __shared__ float Rb[TILE];
    __shared__ float part[8][32];
    __shared__ float psqsh[64];
    __shared__ float red[8];
    __shared__ float qsh;

    // Prologue: uint4 copies of precomputed bf16 splits (L2-resident)
    const uint4* srcA0 = reinterpret_cast<const uint4*>(g_hi + ((size_t)b * NTOT + i0) * KDIM);
    const uint4* srcA1 = reinterpret_cast<const uint4*>(g_lo + ((size_t)b * NTOT + i0) * KDIM);
    const uint4* srcB0 = reinterpret_cast<const uint4*>(g_hi + ((size_t)b * NTOT + j0) * KDIM);
    const uint4* srcB1 = reinterpret_cast<const uint4*>(g_lo + ((size_t)b * NTOT + j0) * KDIM);
    #pragma unroll
    for (int f = tid; f < TILE * 4; f += NTHREADS) {
        int p = f >> 2, q = f & 3;   // point, 8-elem chunk
        *reinterpret_cast<uint4*>(&A0[p * BF_STRIDE + q * 8]) = srcA0[f];
        *reinterpret_cast<uint4*>(&A1[p * BF_STRIDE + q * 8]) = srcA1[f];
        *reinterpret_cast<uint4*>(&B0[p * BF_STRIDE + q * 8]) = srcB0[f];
        *reinterpret_cast<uint4*>(&B1[p * BF_STRIDE + q * 8]) = srcB1[f];
    }
    if (tid < TILE) {
        Ra[tid] = g_sq[b * NTOT + i0 + tid];              // raw; scaled later
    } else {
        Rb[tid - TILE] = g_sq[b * NTOT + j0 + (tid - TILE)];
    }

    // In-block bandwidth reduction (replaces the prep_b launch)
    {
        int k = tid & 31, grp = tid >> 5;
        float cs = 0.0f;
        #pragma unroll
        for (int u = 0; u < 8; u++) cs += g_pcol[b][8 * grp + u][k];
        part[grp][k] = cs;
        if (tid < 64) psqsh[tid] = g_psq[b][tid];
    }
    __syncthreads();
    if (tid < 32) {
        float cs = 0.0f;
        #pragma unroll
        for (int gg = 0; gg < 8; gg++) cs += part[gg][tid];
        float m2 = cs * cs;
        float ss = psqsh[tid] + psqsh[tid + 32];
        #pragma unroll
        for (int off = 16; off > 0; off >>= 1) {
            m2 += __shfl_xor_sync(0xffffffffu, m2, off);
            ss += __shfl_xor_sync(0xffffffffu, ss, off);
        }
        if (tid == 0) {
            const float n = (float)NTOT;
            float sumL2 = 2.0f * n * ss - 2.0f * m2;
            float bw = sumL2 / (n * n - n + 1e-8f);
            bw *= 0.25f;  // / KERNEL_MUL ** (KERNEL_NUM // 2)
            float q = 1.0f / (16.0f * bw);
            qsh = q * 1.4426950408889634f;  // qlog
        }
    }
    __syncthreads();
    const float qlog = qsh;
    const float nq = -qlog;
    // Scale Ra/Rb in place (same thread that wrote them; published by the
    // post-mainloop barrier before any epilogue read)
    if (tid < TILE) Ra[tid] *= nq;
    else            Rb[tid - TILE] *= nq;

    // Mainloop: each warp computes rows [16w,16w+16) x all 128 j.
    float acc[16][4];
    #pragma unroll
    for (int nt = 0; nt < 16; nt++)
        #pragma unroll
        for (int u = 0; u < 4; u++) acc[nt][u] = 0.0f;

    const int arow = 16 * w + (lane & 15);
    #pragma unroll
    for (int ks = 0; ks < 2; ks++) {
        const int k0 = 16 * ks;
        const int acol = k0 + ((lane >> 4) << 3);
        unsigned int a0[4], a1[4];
        ldsm_x4(a0, su32(&A0[arow * BF_STRIDE + acol]));
        ldsm_x4(a1, su32(&A1[arow * BF_STRIDE + acol]));
        const int brow = ((lane >> 4) << 3) + (lane & 7);
        const int bcol = k0 + (lane & 8);
        #pragma unroll
        for (int nt2 = 0; nt2 < 8; nt2++) {
            unsigned int bb0[4], bb1[4];
            ldsm_x4(bb0, su32(&B0[(16 * nt2 + brow) * BF_STRIDE + bcol]));
            ldsm_x4(bb1, su32(&B1[(16 * nt2 + brow) * BF_STRIDE + bcol]));
            mma_bf16(acc[2 * nt2],     a0, bb0);      // hi*hi
            mma_bf16(acc[2 * nt2],     a0, bb1);      // hi*lo
            mma_bf16(acc[2 * nt2],     a1, bb0);      // lo*hi
            mma_bf16(acc[2 * nt2 + 1], a0, bb0 + 2);
            mma_bf16(acc[2 * nt2 + 1], a0, bb1 + 2);
            mma_bf16(acc[2 * nt2 + 1], a1, bb0 + 2);
        }
    }
    __syncthreads();   // publish scaled Ra/Rb for epilogue reads

    // Epilogue. D frag: rows r=16w+g, r+8 (g=lane>>2); cols j=8nt+2*(lane&3)+{0,1}
    // arg = c2*dot - qlog*(sq_i+sq_j); e=2^arg, g4=2^(4*arg);
    // sum = fma(e,e,e) + fma(g4,g4,g4) + (g4^2)^2 = e+e2 + e4+e8 + e16.
    const float c2 = 2.0f * qlog;
    const int g = lane >> 2;
    const float nra0 = Ra[16 * w + g];
    const float nra1 = Ra[16 * w + g + 8];
    const int jb = 2 * (lane & 3);
    float tsA = 0.0f, tsB = 0.0f, tsC = 0.0f;
    #pragma unroll
    for (int nt = 0; nt < 16; nt++) {
        float2 nrb = *reinterpret_cast<const float2*>(&Rb[8 * nt + jb]);
        float args[4] = {
            fmaf(acc[nt][0], c2, nra0 + nrb.x),
            fmaf(acc[nt][1], c2, nra0 + nrb.y),
            fmaf(acc[nt][2], c2, nra1 + nrb.x),
            fmaf(acc[nt][3], c2, nra1 + nrb.y),
        };
        #pragma unroll
        for (int u = 0; u < 4; u++) {
            float e  = ex2f(args[u]);
            float g4 = ex2f(4.0f * args[u]);
            float g2 = g4 * g4;                 // e^8
            tsA += fmaf(e, e, e);               // e + e^2
            tsB += fmaf(g4, g4, g4);            // e^4 + e^8
            tsC = fmaf(g2, g2, tsC);            // e^16
        }
    }
    float tsum = (tsA + tsB) + tsC;

    // Warp-shuffle reduction, then tiny cross-warp pass
    #pragma unroll
    for (int off = 16; off > 0; off >>= 1)
        tsum += __shfl_xor_sync(0xffffffffu, tsum, off);
    if (lane == 0) red[w] = tsum;
    __syncthreads();
    if (tid == 0) {
        float blocksum = 0.0f;
        #pragma unroll
        for (int u = 0; u < 8; u++) blocksum += red[u];
        double wgt = (bx == by) ? 1.0 : 2.0;
        double sgn = ((bx < NTILES / 2) == (by < NTILES / 2)) ? wgt : -wgt;
        atomicAdd(&g_acc[b], sgn * (double)blocksum);
        __threadfence();
        int v = atomicAdd(&g_done, 1);
        if (v == NTRI * BATCH - 1) {
            double scale = exp(1e-8) / ((double)NS * (double)NS);
            #pragma unroll
            for (int q = 0; q < BATCH; q++)
                out[q] = (float)(g_acc[q] * scale);
        }
    }
}

extern "C" void kernel_launch(void* const* d_in, const int* in_sizes, int n_in,
                              void* d_out, int out_size) {
    const float* src = (const float*)d_in[0];
    const float* tgt = (const float*)d_in[1];
    float* out = (float*)d_out;

    mmd_prep_a<<<dim3(PREP_BLOCKS, BATCH), 256>>>(src, tgt);
    mmd_pairs<<<dim3(NTRI, 1, BATCH), NTHREADS>>>(out);
}